// round 11
// baseline (speedup 1.0000x reference)
#include <cuda_runtime.h>
#include <math.h>
#include <stdint.h>

// ---------------------------------------------------------------------------
// Problem constants
// ---------------------------------------------------------------------------
#define BATCH 4
#define CIN   512
#define CC    256
#define CQ    32
#define NN    4096
#define COUT  512

#define PPLANE  ((size_t)NN*(size_t)NN)        // floats per P plane (per z)

// Static device scratch
__device__ __align__(16) float g_qkt[(size_t)8*BATCH*NN*32];       // [plane4][hi/lo][b][n][32]
__device__ __align__(16) float g_v[(size_t)2*BATCH*CC*NN];         // [branch][b][c][n] tf32
__device__ __align__(16) float g_p[(size_t)8*PPLANE];              // [z][n][m] tf32
__device__ __align__(16) float g_lpart[8*32*NN];                   // [z][mtile][n]
__device__ __align__(16) float g_cat[(size_t)BATCH*CIN*NN];        // tf32
__device__ __align__(16) float g_wt[COUT*CIN];                     // Wc tf32

// ---------------------------------------------------------------------------
// Helpers
// ---------------------------------------------------------------------------
__device__ __forceinline__ float tf32r(float x) {
    uint32_t r;
    asm("cvt.rna.tf32.f32 %0, %1;" : "=r"(r) : "f"(x));
    return __uint_as_float(r);
}
__device__ __forceinline__ uint32_t smem_u32(const void* p) {
    uint32_t a;
    asm("{ .reg .u64 t; cvta.to.shared.u64 t, %1; cvt.u32.u64 %0, t; }" : "=r"(a) : "l"(p));
    return a;
}
__device__ __forceinline__ void cpasync16(uint32_t dst, const void* src) {
    asm volatile("cp.async.ca.shared.global [%0], [%1], 16;" :: "r"(dst), "l"(src));
}
#define CP_COMMIT()  asm volatile("cp.async.commit_group;" ::: "memory")
#define CP_WAIT(n)   asm volatile("cp.async.wait_group %0;" :: "n"(n) : "memory")

__device__ __forceinline__ void mma_tf32(float d[4], const uint32_t a[4],
                                         uint32_t b0, uint32_t b1) {
    asm volatile("mma.sync.aligned.m16n8k8.row.col.f32.tf32.tf32.f32 "
                 "{%0,%1,%2,%3}, {%4,%5,%6,%7}, {%8,%9}, {%0,%1,%2,%3};"
                 : "+f"(d[0]), "+f"(d[1]), "+f"(d[2]), "+f"(d[3])
                 : "r"(a[0]), "r"(a[1]), "r"(a[2]), "r"(a[3]), "r"(b0), "r"(b1));
}

// Fast exp: FMA/ALU only (no MUFU). rel err ~2e-7 for |x| < 60.
__device__ __forceinline__ float fexp(float x) {
    float t = x * 1.4426950408889634f;
    float z = t + 12582912.0f;
    int   i = __float_as_int(z);
    float r = z - 12582912.0f;
    float d = t - r;
    float q = fmaf(d, 1.5403530e-4f, 1.3333558e-3f);
    q = fmaf(d, q, 9.6181291e-3f);
    q = fmaf(d, q, 5.5504109e-2f);
    q = fmaf(d, q, 2.4022651e-1f);
    q = fmaf(d, q, 6.9314718e-1f);
    q = fmaf(d, q, 1.0f);
    return __int_as_float(__float_as_int(q) + (i << 23));
}

// ---------------------------------------------------------------------------
// Scalar fp32 GEMM body (proj only): 32(O) x 256(N) tile
// ---------------------------------------------------------------------------
__device__ __forceinline__
void gemm_acc(const float* __restrict__ W, const float* __restrict__ Xb,
              int Kd, int o0, int n0, float acc[4][8],
              float Ws[32][32], float Xs[32][256])
{
    const int t  = threadIdx.x;
    const int tx = t & 31;
    const int ty = t >> 5;
#pragma unroll
    for (int i = 0; i < 4; i++)
#pragma unroll
        for (int j = 0; j < 8; j++) acc[i][j] = 0.f;

    for (int k0 = 0; k0 < Kd; k0 += 32) {
        {
            int l = t * 4;
            int r = l >> 5, c = l & 31;
            *(float4*)&Ws[r][c] = *(const float4*)(W + (size_t)(o0 + r) * Kd + k0 + c);
        }
#pragma unroll
        for (int u = 0; u < 8; u++) {
            int f = t + 256 * u;
            int r = f >> 6;
            int c = (f & 63) * 4;
            *(float4*)&Xs[r][c] = *(const float4*)(Xb + (size_t)(k0 + r) * NN + n0 + c);
        }
        __syncthreads();
#pragma unroll
        for (int kk = 0; kk < 32; kk++) {
            float4 xa = *(const float4*)&Xs[kk][tx * 4];
            float4 xb = *(const float4*)&Xs[kk][tx * 4 + 128];
            float wv[4];
#pragma unroll
            for (int i = 0; i < 4; i++) wv[i] = Ws[ty * 4 + i][kk];
#pragma unroll
            for (int i = 0; i < 4; i++) {
                acc[i][0] += wv[i] * xa.x; acc[i][1] += wv[i] * xa.y;
                acc[i][2] += wv[i] * xa.z; acc[i][3] += wv[i] * xa.w;
                acc[i][4] += wv[i] * xb.x; acc[i][5] += wv[i] * xb.y;
                acc[i][6] += wv[i] * xb.z; acc[i][7] += wv[i] * xb.w;
            }
        }
        __syncthreads();
    }
}

// ---------------------------------------------------------------------------
// Projections: one launch, grid (16, 20, BATCH)
//   sy 0..3 : q1,k1,q2,k2 -> TRANSPOSED hi/lo tf32 planes [n][32]
//   sy 4..19: v1/v2 o-tiles -> tf32 planes [c][n]
// ---------------------------------------------------------------------------
__global__ __launch_bounds__(256)
void proj_kernel(const float* __restrict__ x,
                 const float* __restrict__ Wq1, const float* __restrict__ bq1,
                 const float* __restrict__ Wk1, const float* __restrict__ bk1,
                 const float* __restrict__ Wv1, const float* __restrict__ bv1,
                 const float* __restrict__ Wq2, const float* __restrict__ bq2,
                 const float* __restrict__ Wk2, const float* __restrict__ bk2,
                 const float* __restrict__ Wv2, const float* __restrict__ bv2)
{
    __shared__ float Ws[32][32];
    __shared__ float Xs[32][256];

    const int sy = blockIdx.y;
    const int bz = blockIdx.z;
    const int n0 = blockIdx.x * 256;
    const int t  = threadIdx.x;
    const int tx = t & 31, ty = t >> 5;
    const size_t XB = (size_t)bz * CIN * NN;
    float acc[4][8];

    if (sy < 4) {
        const float *W, *bias, *Xb;
        switch (sy) {
            case 0:  W = Wq1; bias = bq1; Xb = x + XB;           break;
            case 1:  W = Wk1; bias = bk1; Xb = x + XB;           break;
            case 2:  W = Wq2; bias = bq2; Xb = x + XB + CC * NN; break;
            default: W = Wk2; bias = bk2; Xb = x + XB + CC * NN; break;
        }
        float* Th = g_qkt + ((size_t)(sy * 2 + 0) * BATCH + bz) * (size_t)NN * 32;
        float* Tl = g_qkt + ((size_t)(sy * 2 + 1) * BATCH + bz) * (size_t)NN * 32;
        gemm_acc(W, Xb, CC, 0, n0, acc, Ws, Xs);
#pragma unroll
        for (int i = 0; i < 4; i++) {
            int o = ty * 4 + i;
            float bv = bias[o];
#pragma unroll
            for (int j = 0; j < 8; j++) {
                int n = n0 + tx * 4 + (j & 3) + ((j >= 4) ? 128 : 0);
                float s  = acc[i][j] + bv;
                float hi = tf32r(s);
                Th[(size_t)n * 32 + o] = hi;
                Tl[(size_t)n * 32 + o] = tf32r(s - hi);
            }
        }
    } else {
        int vsl = sy - 4;
        int br  = vsl >> 3;
        int o0  = (vsl & 7) * 32;
        const float* W    = br ? Wv2 : Wv1;
        const float* bias = br ? bv2 : bv1;
        const float* Xb   = x + XB + (size_t)br * CC * NN;
        float* Vb = g_v + ((size_t)br * BATCH + bz) * (size_t)CC * NN;

        gemm_acc(W, Xb, CC, o0, n0, acc, Ws, Xs);
#pragma unroll
        for (int i = 0; i < 4; i++) {
            int o = o0 + ty * 4 + i;
            float bv = bias[o];
            float v[8];
#pragma unroll
            for (int j = 0; j < 8; j++) v[j] = tf32r(acc[i][j] + bv);
            *(float4*)(Vb + (size_t)o * NN + n0 + tx * 4)       = make_float4(v[0], v[1], v[2], v[3]);
            *(float4*)(Vb + (size_t)o * NN + n0 + tx * 4 + 128) = make_float4(v[4], v[5], v[6], v[7]);
        }
    }
}

// ---------------------------------------------------------------------------
// QK on tensor cores (split-tf32 3-combo: hh + hl + lh) + exp + P + partials.
// CTA: 128q x 128m, 8 warps (wq 0..3 x wm 0..1), warp tile 32q x 64m.
// grid (32 mx, 32 qy, 8 z), 256 threads, dyn smem 73728 B (2 CTA/SM).
// ---------------------------------------------------------------------------
#define QK_PL  (128*36)                // floats per smem plane
extern __shared__ float dyn_sm[];

__global__ __launch_bounds__(256, 2)
void qk_mma_kernel()
{
    float* sm = dyn_sm;
    const int t    = threadIdx.x;
    const int lane = t & 31;
    const int warp = t >> 5;
    const int wq   = warp & 3;
    const int wm   = warp >> 2;
    const int mx   = blockIdx.x;
    const int qy   = blockIdx.y;
    const int z    = blockIdx.z;
    const int b    = z >> 1, a = z & 1;
    const int n0   = qy * 128, m0 = mx * 128;

    const int qpl = (a == 0) ? 2 : 0;
    const int kpl = (a == 0) ? 1 : 3;
    const float* srcs[4] = {
        g_qkt + ((size_t)(qpl * 2 + 0) * BATCH + b) * (size_t)NN * 32 + (size_t)n0 * 32,
        g_qkt + ((size_t)(qpl * 2 + 1) * BATCH + b) * (size_t)NN * 32 + (size_t)n0 * 32,
        g_qkt + ((size_t)(kpl * 2 + 0) * BATCH + b) * (size_t)NN * 32 + (size_t)m0 * 32,
        g_qkt + ((size_t)(kpl * 2 + 1) * BATCH + b) * (size_t)NN * 32 + (size_t)m0 * 32
    };
    const uint32_t sm0 = smem_u32(sm);

#pragma unroll
    for (int p = 0; p < 4; p++) {
        uint32_t dst = sm0 + (uint32_t)(p * QK_PL) * 4;
#pragma unroll
        for (int i = 0; i < 4; i++) {
            int f = t + 256 * i;
            int row = f >> 3, sg = f & 7;
            cpasync16(dst + (uint32_t)(row * 36 + sg * 4) * 4,
                      srcs[p] + (size_t)row * 32 + sg * 4);
        }
    }
    CP_COMMIT();
    CP_WAIT(0);
    __syncthreads();

    float acc[2][8][4];
#pragma unroll
    for (int mt = 0; mt < 2; mt++)
#pragma unroll
        for (int nt = 0; nt < 8; nt++)
#pragma unroll
            for (int e = 0; e < 4; e++) acc[mt][nt][e] = 0.f;

    const int r4 = lane >> 2;
    const int c4 = lane & 3;

#pragma unroll
    for (int combo = 0; combo < 3; combo++) {
        const float* As = sm + ((combo == 2) ? 1 : 0) * QK_PL;
        const float* Bs = sm + ((combo == 1) ? 3 : 2) * QK_PL;
#pragma unroll
        for (int ks = 0; ks < 4; ks++) {
            const int kcol = ks * 8 + c4;
            uint32_t A[2][4];
#pragma unroll
            for (int mt = 0; mt < 2; mt++) {
                const int rb = wq * 32 + mt * 16;
                A[mt][0] = __float_as_uint(As[(rb + r4)     * 36 + kcol]);
                A[mt][1] = __float_as_uint(As[(rb + r4 + 8) * 36 + kcol]);
                A[mt][2] = __float_as_uint(As[(rb + r4)     * 36 + kcol + 4]);
                A[mt][3] = __float_as_uint(As[(rb + r4 + 8) * 36 + kcol + 4]);
            }
#pragma unroll
            for (int nt = 0; nt < 8; nt++) {
                const int mb = wm * 64 + nt * 8;
                uint32_t B0 = __float_as_uint(Bs[(mb + r4) * 36 + kcol]);
                uint32_t B1 = __float_as_uint(Bs[(mb + r4) * 36 + kcol + 4]);
                mma_tf32(acc[0][nt], A[0], B0, B1);
                mma_tf32(acc[1][nt], A[1], B0, B1);
            }
        }
    }
    __syncthreads();   // done reading Q/K smem; reuse it as stage

    // exp + stage (q x m, pitch 132) + row-sum partials
    float* stage = sm;                 // 128*132 = 16896 floats
    float* ssum  = sm + 16896;         // [128][2]
    float rs[2][2] = {{0.f, 0.f}, {0.f, 0.f}};
#pragma unroll
    for (int mt = 0; mt < 2; mt++)
#pragma unroll
        for (int nt = 0; nt < 8; nt++)
#pragma unroll
            for (int e = 0; e < 4; e++) {
                int q = wq * 32 + mt * 16 + r4 + ((e >= 2) ? 8 : 0);
                int m = wm * 64 + nt * 8 + 2 * c4 + (e & 1);
                float p = tf32r(fexp(acc[mt][nt][e]));
                stage[q * 132 + m] = p;
                rs[mt][e >> 1] += p;
            }
#pragma unroll
    for (int sh = 1; sh < 4; sh <<= 1) {
#pragma unroll
        for (int mt = 0; mt < 2; mt++)
#pragma unroll
            for (int hf = 0; hf < 2; hf++)
                rs[mt][hf] += __shfl_xor_sync(0xffffffffu, rs[mt][hf], sh);
    }
    if (c4 == 0) {
#pragma unroll
        for (int mt = 0; mt < 2; mt++) {
            int q0 = wq * 32 + mt * 16 + r4;
            ssum[q0 * 2 + wm]       = rs[mt][0];
            ssum[(q0 + 8) * 2 + wm] = rs[mt][1];
        }
    }
    __syncthreads();

    if (t < 128)
        g_lpart[((size_t)z * 32 + mx) * NN + n0 + t] = ssum[t * 2] + ssum[t * 2 + 1];

    // coalesced P write
    {
        const int q  = t >> 1;
        const int mh = (t & 1) * 64;
        float* dst = g_p + (size_t)z * PPLANE + (size_t)(n0 + q) * NN + m0 + mh;
        const float* src = stage + q * 132 + mh;
#pragma unroll
        for (int u = 0; u < 16; u++)
            *(float4*)(dst + u * 4) = *(const float4*)(src + u * 4);
    }
}

// ---------------------------------------------------------------------------
// PV via mma.sync tf32. CTA: 64q x 256c (2 CTAs/SM).
// 8 warps (wq 0..1 x wc 0..3), warp tile 32q x 64c, acc 2x8x4.
// K in 32-chunks, double-buffered cp.async. Staged coalesced writeout.
// grid (64 qb, 8 z), 256 threads, dyn smem 92160 B.
// ---------------------------------------------------------------------------
#define PV_A0 0
#define PV_A1 (64*36)                  // 2304
#define PV_B0 (2*64*36)                // 4608
#define PV_B1 (PV_B0 + 256*36)         // 13824
#define PV_SMEM_FLOATS (PV_B1 + 256*36)   // 23040 floats = 92160 B

__global__ __launch_bounds__(256, 2)
void pv_mma_kernel()
{
    float* sm = dyn_sm;
    const int t    = threadIdx.x;
    const int lane = t & 31;
    const int warp = t >> 5;
    const int wq   = warp & 1;          // q-group of 32
    const int wc   = warp >> 1;         // c-group of 64 (0..3)
    const int qb   = blockIdx.x;
    const int z    = blockIdx.y;
    const int b    = z >> 1, a = z & 1;
    const int n0   = qb * 64;

    const float* P = g_p + (size_t)z * PPLANE + (size_t)n0 * NN;
    const float* V = g_v + ((size_t)a * BATCH + b) * (size_t)CC * NN;
    const uint32_t sm0 = smem_u32(sm);

    auto load_chunk = [&](int buf, int kc) {
        const int m0 = kc * 32;
        const uint32_t pd = sm0 + (uint32_t)(buf ? PV_A1 : PV_A0) * 4;
        const uint32_t vd = sm0 + (uint32_t)(buf ? PV_B1 : PV_B0) * 4;
#pragma unroll
        for (int i = 0; i < 2; i++) {           // P: 64 rows x 32 k
            int f = t + 256 * i;
            int row = f >> 3, c4i = f & 7;
            cpasync16(pd + (uint32_t)(row * 36 + c4i * 4) * 4,
                      P + (size_t)row * NN + m0 + c4i * 4);
        }
#pragma unroll
        for (int i = 0; i < 8; i++) {           // V: 256 rows x 32 k
            int f = t + 256 * i;
            int row = f >> 3, c4i = f & 7;
            cpasync16(vd + (uint32_t)(row * 36 + c4i * 4) * 4,
                      V + (size_t)row * NN + m0 + c4i * 4);
        }
        CP_COMMIT();
    };

    float acc[2][8][4];
#pragma unroll
    for (int mt = 0; mt < 2; mt++)
#pragma unroll
        for (int nt = 0; nt < 8; nt++)
#pragma unroll
            for (int e = 0; e < 4; e++) acc[mt][nt][e] = 0.f;

    const int r4 = lane >> 2;
    const int c4 = lane & 3;

    load_chunk(0, 0);
    for (int kc = 0; kc < 128; kc++) {
        const int buf = kc & 1;
        if (kc < 127) load_chunk(buf ^ 1, kc + 1);
        if (kc < 127) { CP_WAIT(1); } else { CP_WAIT(0); }
        __syncthreads();

        const float* Ps = sm + (buf ? PV_A1 : PV_A0);
        const float* Vs = sm + (buf ? PV_B1 : PV_B0);
#pragma unroll
        for (int ks = 0; ks < 4; ks++) {
            const int kcol = ks * 8 + c4;
            uint32_t A[2][4];
#pragma unroll
            for (int mt = 0; mt < 2; mt++) {
                const int rb = wq * 32 + mt * 16;
                A[mt][0] = __float_as_uint(Ps[(rb + r4)     * 36 + kcol]);
                A[mt][1] = __float_as_uint(Ps[(rb + r4 + 8) * 36 + kcol]);
                A[mt][2] = __float_as_uint(Ps[(rb + r4)     * 36 + kcol + 4]);
                A[mt][3] = __float_as_uint(Ps[(rb + r4 + 8) * 36 + kcol + 4]);
            }
#pragma unroll
            for (int nt = 0; nt < 8; nt++) {
                const int cb = wc * 64 + nt * 8;
                uint32_t B0 = __float_as_uint(Vs[(cb + r4) * 36 + kcol]);
                uint32_t B1 = __float_as_uint(Vs[(cb + r4) * 36 + kcol + 4]);
                mma_tf32(acc[0][nt], A[0], B0, B1);
                mma_tf32(acc[1][nt], A[1], B0, B1);
            }
        }
        __syncthreads();
    }

    // row-sum normalizers -> sm[0..63] (A region, free now)
    if (t < 64) {
        float s = 0.f;
#pragma unroll
        for (int x = 0; x < 32; x++)
            s += g_lpart[((size_t)z * 32 + x) * NN + n0 + t];
        sm[t] = 1.f / s;
    }
    __syncthreads();

    // staged coalesced writeout: two c-halves of 128 through B0.. region
    float* stage = sm + PV_B0;          // 128 x pitch-68 floats (8704 <= 9216)
    const int crow = t >> 1;            // 0..127
    const int qh4  = (t & 1) * 32;
    for (int h = 0; h < 2; h++) {
        if ((wc >> 1) == h) {
#pragma unroll
            for (int mt = 0; mt < 2; mt++)
#pragma unroll
                for (int nt = 0; nt < 8; nt++)
#pragma unroll
                    for (int e = 0; e < 4; e++) {
                        int ql = wq * 32 + mt * 16 + r4 + ((e >= 2) ? 8 : 0);
                        int cl = (wc & 1) * 64 + nt * 8 + 2 * c4 + (e & 1);
                        stage[cl * 68 + ql] = tf32r(acc[mt][nt][e] * sm[ql]);
                    }
        }
        __syncthreads();
        {
            float* dst = g_cat + ((size_t)b * CIN + a * 256 + h * 128 + crow) * NN + n0 + qh4;
            const float* src = stage + crow * 68 + qh4;
#pragma unroll
            for (int u = 0; u < 8; u++)
                *(float4*)(dst + u * 4) = *(const float4*)(src + u * 4);
        }
        __syncthreads();
    }
}

// ---------------------------------------------------------------------------
// Round Wc to tf32 (rna) into g_wt.
// ---------------------------------------------------------------------------
__global__ __launch_bounds__(256)
void round_w_kernel(const float* __restrict__ W)
{
    int i = blockIdx.x * 256 + threadIdx.x;
    float4 v = ((const float4*)W)[i];
    v.x = tf32r(v.x); v.y = tf32r(v.y); v.z = tf32r(v.z); v.w = tf32r(v.w);
    ((float4*)g_wt)[i] = v;
}

// ---------------------------------------------------------------------------
// Final 1x1 conv on tf32 mma + BN(eval) + LeakyReLU fused. (unchanged R10)
// ---------------------------------------------------------------------------
#define OC_A0 0
#define OC_A1 (128*36)
#define OC_B0 (2*128*36)
#define OC_B1 (OC_B0 + 32*136)
#define OC_SMEM_FLOATS (OC_B1 + 32*136)   // 17920 floats = 71680 B

__global__ __launch_bounds__(256)
void outconv_mma_kernel(const float* __restrict__ bias, float* __restrict__ Y,
                        const float* __restrict__ gamma, const float* __restrict__ beta)
{
    float* sm = dyn_sm;
    const int t    = threadIdx.x;
    const int lane = t & 31;
    const int warp = t >> 5;
    const int wq   = warp & 3;
    const int wc   = warp >> 2;
    const int nb0  = blockIdx.x * 128;
    const int o0   = blockIdx.y * 128;
    const int b    = blockIdx.z;

    const float* Wt = g_wt + (size_t)o0 * CIN;
    const float* X  = g_cat + (size_t)b * CIN * NN;
    float* Yb = Y + (size_t)b * COUT * NN;
    const uint32_t sm0 = smem_u32(sm);

    auto load_chunk = [&](int buf, int kc) {
        const int k0 = kc * 32;
        const uint32_t ad = sm0 + (uint32_t)(buf ? OC_A1 : OC_A0) * 4;
        const uint32_t bd = sm0 + (uint32_t)(buf ? OC_B1 : OC_B0) * 4;
#pragma unroll
        for (int i = 0; i < 4; i++) {
            int f = t + 256 * i;
            int row = f >> 3, c4i = f & 7;
            cpasync16(ad + (uint32_t)(row * 36 + c4i * 4) * 4,
                      Wt + (size_t)row * CIN + k0 + c4i * 4);
        }
#pragma unroll
        for (int i = 0; i < 4; i++) {
            int f = t + 256 * i;
            int row = f >> 5, c4i = f & 31;
            cpasync16(bd + (uint32_t)(row * 136 + c4i * 4) * 4,
                      X + (size_t)(k0 + row) * NN + nb0 + c4i * 4);
        }
        CP_COMMIT();
    };

    float acc[2][8][4];
#pragma unroll
    for (int mt = 0; mt < 2; mt++)
#pragma unroll
        for (int nt = 0; nt < 8; nt++)
#pragma unroll
            for (int e = 0; e < 4; e++) acc[mt][nt][e] = 0.f;

    const int r4 = lane >> 2;
    const int c4 = lane & 3;

    load_chunk(0, 0);
    for (int kc = 0; kc < 16; kc++) {
        const int buf = kc & 1;
        if (kc < 15) load_chunk(buf ^ 1, kc + 1);
        if (kc < 15) { CP_WAIT(1); } else { CP_WAIT(0); }
        __syncthreads();

        const float* As = sm + (buf ? OC_A1 : OC_A0);
        const float* Bs = sm + (buf ? OC_B1 : OC_B0);
#pragma unroll
        for (int ks = 0; ks < 4; ks++) {
            const int kcol = ks * 8 + c4;
            uint32_t A[2][4];
#pragma unroll
            for (int mt = 0; mt < 2; mt++) {
                const int rb = wq * 32 + mt * 16;
                A[mt][0] = __float_as_uint(As[(rb + r4)     * 36 + kcol]);
                A[mt][1] = __float_as_uint(As[(rb + r4 + 8) * 36 + kcol]);
                A[mt][2] = __float_as_uint(As[(rb + r4)     * 36 + kcol + 4]);
                A[mt][3] = __float_as_uint(As[(rb + r4 + 8) * 36 + kcol + 4]);
            }
#pragma unroll
            for (int nt = 0; nt < 8; nt++) {
                const int nb = wc * 64 + nt * 8;
                uint32_t B0 = __float_as_uint(Bs[kcol * 136 + nb + r4]);
                uint32_t B1 = __float_as_uint(Bs[(kcol + 4) * 136 + nb + r4]);
                mma_tf32(acc[0][nt], A[0], B0, B1);
                mma_tf32(acc[1][nt], A[1], B0, B1);
            }
        }
        __syncthreads();
    }

    float* stage = sm;   // 128*132 floats
#pragma unroll
    for (int mt = 0; mt < 2; mt++)
#pragma unroll
        for (int nt = 0; nt < 8; nt++)
#pragma unroll
            for (int e = 0; e < 4; e++) {
                int ol = wq * 32 + mt * 16 + r4 + ((e >= 2) ? 8 : 0);
                int nl = wc * 64 + nt * 8 + 2 * c4 + (e & 1);
                stage[ol * 132 + nl] = acc[mt][nt][e];
            }
    __syncthreads();

    const float inv_bn = rsqrtf(1.0f + 1e-5f);
    {
        const int ol = t >> 1;
        const int o  = o0 + ol;
        const int nc = (t & 1) * 64;
        const float bv = bias[o];
        const float g  = gamma[o] * inv_bn;
        const float be = beta[o];
        float* dst = Yb + (size_t)o * NN + nb0 + nc;
        const float* src = stage + ol * 132 + nc;
#pragma unroll
        for (int u = 0; u < 16; u++) {
            float4 v = *(const float4*)(src + u * 4);
            float w[4] = {v.x, v.y, v.z, v.w};
#pragma unroll
            for (int q = 0; q < 4; q++) {
                float y = w[q] + bv;
                y = y * g + be;
                w[q] = (y > 0.f) ? y : 0.2f * y;
            }
            *(float4*)(dst + u * 4) = make_float4(w[0], w[1], w[2], w[3]);
        }
    }
}

// ---------------------------------------------------------------------------
// Launch
// ---------------------------------------------------------------------------
extern "C" void kernel_launch(void* const* d_in, const int* in_sizes, int n_in,
                              void* d_out, int out_size)
{
    const float* x   = (const float*)d_in[0];
    const float* Wq1 = (const float*)d_in[1];
    const float* bq1 = (const float*)d_in[2];
    const float* Wk1 = (const float*)d_in[3];
    const float* bk1 = (const float*)d_in[4];
    const float* Wv1 = (const float*)d_in[5];
    const float* bv1 = (const float*)d_in[6];
    const float* Wq2 = (const float*)d_in[7];
    const float* bq2 = (const float*)d_in[8];
    const float* Wk2 = (const float*)d_in[9];
    const float* bk2 = (const float*)d_in[10];
    const float* Wv2 = (const float*)d_in[11];
    const float* bv2 = (const float*)d_in[12];
    const float* Wc  = (const float*)d_in[13];
    const float* bc  = (const float*)d_in[14];
    const float* gam = (const float*)d_in[15];
    const float* bet = (const float*)d_in[16];
    float* out = (float*)d_out;

    proj_kernel<<<dim3(16, 20, BATCH), 256>>>(x,
        Wq1, bq1, Wk1, bk1, Wv1, bv1,
        Wq2, bq2, Wk2, bk2, Wv2, bv2);

    round_w_kernel<<<256, 256>>>(Wc);

    const int qk_smem = (4 * QK_PL) * (int)sizeof(float);      // 73728 B
    cudaFuncSetAttribute(qk_mma_kernel,
                         cudaFuncAttributeMaxDynamicSharedMemorySize, qk_smem);
    qk_mma_kernel<<<dim3(32, 32, 8), 256, qk_smem>>>();

    const int pv_smem = PV_SMEM_FLOATS * (int)sizeof(float);   // 92160 B
    cudaFuncSetAttribute(pv_mma_kernel,
                         cudaFuncAttributeMaxDynamicSharedMemorySize, pv_smem);
    pv_mma_kernel<<<dim3(64, 8), 256, pv_smem>>>();

    const int oc_smem = OC_SMEM_FLOATS * (int)sizeof(float);   // 71680 B
    cudaFuncSetAttribute(outconv_mma_kernel,
                         cudaFuncAttributeMaxDynamicSharedMemorySize, oc_smem);
    outconv_mma_kernel<<<dim3(32, 4, BATCH), 256, oc_smem>>>(bc, out, gam, bet);
}

// round 13
// speedup vs baseline: 1.1588x; 1.1588x over previous
#include <cuda_runtime.h>
#include <math.h>
#include <stdint.h>

// ---------------------------------------------------------------------------
// Problem constants
// ---------------------------------------------------------------------------
#define BATCH 4
#define CIN   512
#define CC    256
#define CQ    32
#define NN    4096
#define COUT  512

#define QKPLANE (BATCH*CQ*NN)                  // floats per Q/K plane
#define PPLANE  ((size_t)NN*(size_t)NN)        // floats per P plane (per z)

// Static device scratch (~600 MB total)
__device__ __align__(16) float g_qk[4*QKPLANE];                    // Q1,K1,Q2,K2
__device__ __align__(16) float g_v[(size_t)2*BATCH*CC*NN];         // [branch][b][c][n] tf32-rounded
__device__ __align__(16) float g_p[(size_t)8*PPLANE];              // [z][n][m] tf32-rounded
__device__ __align__(16) float g_lpart[8*32*NN];                   // [z][ktile][n]
__device__ __align__(16) float g_cat[(size_t)BATCH*CIN*NN];        // tf32-rounded
__device__ __align__(16) float g_wt[COUT*CIN];                     // Wc tf32-rounded

// ---------------------------------------------------------------------------
// Helpers
// ---------------------------------------------------------------------------
__device__ __forceinline__ float tf32r(float x) {
    uint32_t r;
    asm("cvt.rna.tf32.f32 %0, %1;" : "=r"(r) : "f"(x));
    return __uint_as_float(r);
}
__device__ __forceinline__ uint32_t smem_u32(const void* p) {
    uint32_t a;
    asm("{ .reg .u64 t; cvta.to.shared.u64 t, %1; cvt.u32.u64 %0, t; }" : "=r"(a) : "l"(p));
    return a;
}
__device__ __forceinline__ void cpasync16(uint32_t dst, const void* src) {
    asm volatile("cp.async.ca.shared.global [%0], [%1], 16;" :: "r"(dst), "l"(src));
}
#define CP_COMMIT()  asm volatile("cp.async.commit_group;" ::: "memory")
#define CP_WAIT(n)   asm volatile("cp.async.wait_group %0;" :: "n"(n) : "memory")

// m16n8k8 tf32 MMA (sm_80+ PTX; tensor pipe)
__device__ __forceinline__ void mma_tf32(float d[4], const uint32_t a[4],
                                         uint32_t b0, uint32_t b1) {
    asm volatile("mma.sync.aligned.m16n8k8.row.col.f32.tf32.tf32.f32 "
                 "{%0,%1,%2,%3}, {%4,%5,%6,%7}, {%8,%9}, {%0,%1,%2,%3};"
                 : "+f"(d[0]), "+f"(d[1]), "+f"(d[2]), "+f"(d[3])
                 : "r"(a[0]), "r"(a[1]), "r"(a[2]), "r"(a[3]), "r"(b0), "r"(b1));
}

// Fast exp: FMA/ALU only (no MUFU). rel err ~2e-7 for |x| < 60.
__device__ __forceinline__ float fexp(float x) {
    float t = x * 1.4426950408889634f;
    float z = t + 12582912.0f;
    int   i = __float_as_int(z);
    float r = z - 12582912.0f;
    float d = t - r;
    float q = fmaf(d, 1.5403530e-4f, 1.3333558e-3f);
    q = fmaf(d, q, 9.6181291e-3f);
    q = fmaf(d, q, 5.5504109e-2f);
    q = fmaf(d, q, 2.4022651e-1f);
    q = fmaf(d, q, 6.9314718e-1f);
    q = fmaf(d, q, 1.0f);
    return __int_as_float(__float_as_int(q) + (i << 23));
}

// ---------------------------------------------------------------------------
// Scalar fp32 GEMM body (proj only): 32(O) x 256(N) tile
// ---------------------------------------------------------------------------
__device__ __forceinline__
void gemm_acc(const float* __restrict__ W, const float* __restrict__ Xb,
              int Kd, int o0, int n0, float acc[4][8],
              float Ws[32][32], float Xs[32][256])
{
    const int t  = threadIdx.x;
    const int tx = t & 31;
    const int ty = t >> 5;
#pragma unroll
    for (int i = 0; i < 4; i++)
#pragma unroll
        for (int j = 0; j < 8; j++) acc[i][j] = 0.f;

    for (int k0 = 0; k0 < Kd; k0 += 32) {
        {
            int l = t * 4;
            int r = l >> 5, c = l & 31;
            *(float4*)&Ws[r][c] = *(const float4*)(W + (size_t)(o0 + r) * Kd + k0 + c);
        }
#pragma unroll
        for (int u = 0; u < 8; u++) {
            int f = t + 256 * u;
            int r = f >> 6;
            int c = (f & 63) * 4;
            *(float4*)&Xs[r][c] = *(const float4*)(Xb + (size_t)(k0 + r) * NN + n0 + c);
        }
        __syncthreads();
#pragma unroll
        for (int kk = 0; kk < 32; kk++) {
            float4 xa = *(const float4*)&Xs[kk][tx * 4];
            float4 xb = *(const float4*)&Xs[kk][tx * 4 + 128];
            float wv[4];
#pragma unroll
            for (int i = 0; i < 4; i++) wv[i] = Ws[ty * 4 + i][kk];
#pragma unroll
            for (int i = 0; i < 4; i++) {
                acc[i][0] += wv[i] * xa.x; acc[i][1] += wv[i] * xa.y;
                acc[i][2] += wv[i] * xa.z; acc[i][3] += wv[i] * xa.w;
                acc[i][4] += wv[i] * xb.x; acc[i][5] += wv[i] * xb.y;
                acc[i][6] += wv[i] * xb.z; acc[i][7] += wv[i] * xb.w;
            }
        }
        __syncthreads();
    }
}

// ---------------------------------------------------------------------------
// Projections: one launch, grid (16, 20, BATCH)   [R10-proven]
// ---------------------------------------------------------------------------
__global__ __launch_bounds__(256)
void proj_kernel(const float* __restrict__ x,
                 const float* __restrict__ Wq1, const float* __restrict__ bq1,
                 const float* __restrict__ Wk1, const float* __restrict__ bk1,
                 const float* __restrict__ Wv1, const float* __restrict__ bv1,
                 const float* __restrict__ Wq2, const float* __restrict__ bq2,
                 const float* __restrict__ Wk2, const float* __restrict__ bk2,
                 const float* __restrict__ Wv2, const float* __restrict__ bv2)
{
    __shared__ float Ws[32][32];
    __shared__ float Xs[32][256];

    const int sy = blockIdx.y;
    const int bz = blockIdx.z;
    const int n0 = blockIdx.x * 256;
    const int t  = threadIdx.x;
    const int tx = t & 31, ty = t >> 5;
    const size_t XB = (size_t)bz * CIN * NN;
    float acc[4][8];

    if (sy < 4) {
        const float *W, *bias, *Xb;
        float* Yb;
        switch (sy) {
            case 0:  W = Wq1; bias = bq1; Xb = x + XB;           Yb = g_qk + 0*QKPLANE; break;
            case 1:  W = Wk1; bias = bk1; Xb = x + XB;           Yb = g_qk + 1*QKPLANE; break;
            case 2:  W = Wq2; bias = bq2; Xb = x + XB + CC * NN; Yb = g_qk + 2*QKPLANE; break;
            default: W = Wk2; bias = bk2; Xb = x + XB + CC * NN; Yb = g_qk + 3*QKPLANE; break;
        }
        Yb += (size_t)bz * CQ * NN;
        gemm_acc(W, Xb, CC, 0, n0, acc, Ws, Xs);
#pragma unroll
        for (int i = 0; i < 4; i++) {
            int o = ty * 4 + i;
            float bv = bias[o];
            float v[8];
#pragma unroll
            for (int j = 0; j < 8; j++) v[j] = acc[i][j] + bv;
            *(float4*)(Yb + (size_t)o * NN + n0 + tx * 4)       = make_float4(v[0], v[1], v[2], v[3]);
            *(float4*)(Yb + (size_t)o * NN + n0 + tx * 4 + 128) = make_float4(v[4], v[5], v[6], v[7]);
        }
    } else {
        int vsl = sy - 4;
        int br  = vsl >> 3;
        int o0  = (vsl & 7) * 32;
        const float* W    = br ? Wv2 : Wv1;
        const float* bias = br ? bv2 : bv1;
        const float* Xb   = x + XB + (size_t)br * CC * NN;
        float* Vb = g_v + ((size_t)br * BATCH + bz) * (size_t)CC * NN;

        gemm_acc(W, Xb, CC, o0, n0, acc, Ws, Xs);
#pragma unroll
        for (int i = 0; i < 4; i++) {
            int o = o0 + ty * 4 + i;
            float bv = bias[o];
            float v[8];
#pragma unroll
            for (int j = 0; j < 8; j++) v[j] = tf32r(acc[i][j] + bv);
            *(float4*)(Vb + (size_t)o * NN + n0 + tx * 4)       = make_float4(v[0], v[1], v[2], v[3]);
            *(float4*)(Vb + (size_t)o * NN + n0 + tx * 4 + 128) = make_float4(v[4], v[5], v[6], v[7]);
        }
    }
}

// ---------------------------------------------------------------------------
// QK + exp + tf32-rounded P + deterministic row-sum partials  [R10-proven]
// ---------------------------------------------------------------------------
__global__ __launch_bounds__(256)
void qk_exp_kernel()
{
    __shared__ float Qs[32][64];
    __shared__ float Ks[32][128];

    const int t  = threadIdx.x;
    const int kx = blockIdx.x;
    const int qy = blockIdx.y;
    const int z  = blockIdx.z;   // b*2 + a
    const int b  = z >> 1, a = z & 1;

    const float* Q = g_qk + (a == 0 ? 2 : 0) * QKPLANE + (size_t)b * CQ * NN;
    const float* K = g_qk + (a == 0 ? 1 : 3) * QKPLANE + (size_t)b * CQ * NN;
    const int n0 = qy * 64, m0 = kx * 128;

#pragma unroll
    for (int it = 0; it < 2; it++) {
        int f = t + 256 * it;
        int d = f >> 4, c = (f & 15) * 4;
        *(float4*)&Qs[d][c] = *(const float4*)(Q + (size_t)d * NN + n0 + c);
    }
#pragma unroll
    for (int it = 0; it < 4; it++) {
        int f = t + 256 * it;
        int d = f >> 5, c = (f & 31) * 4;
        *(float4*)&Ks[d][c] = *(const float4*)(K + (size_t)d * NN + m0 + c);
    }
    __syncthreads();

    const int ig = t >> 4;
    const int jg = t & 15;

    float acc[4][8];
#pragma unroll
    for (int r = 0; r < 4; r++)
#pragma unroll
        for (int c = 0; c < 8; c++) acc[r][c] = 0.f;

#pragma unroll
    for (int d = 0; d < 32; d++) {
        float4 q4 = *(const float4*)&Qs[d][ig * 4];
        float4 ka = *(const float4*)&Ks[d][jg * 8];
        float4 kb = *(const float4*)&Ks[d][jg * 8 + 4];
        float qv[4] = {q4.x, q4.y, q4.z, q4.w};
#pragma unroll
        for (int r = 0; r < 4; r++) {
            acc[r][0] += qv[r] * ka.x; acc[r][1] += qv[r] * ka.y;
            acc[r][2] += qv[r] * ka.z; acc[r][3] += qv[r] * ka.w;
            acc[r][4] += qv[r] * kb.x; acc[r][5] += qv[r] * kb.y;
            acc[r][6] += qv[r] * kb.z; acc[r][7] += qv[r] * kb.w;
        }
    }

    float* P = g_p + (size_t)z * PPLANE;

#pragma unroll
    for (int r = 0; r < 4; r++) {
        float p[8];
        float sum = 0.f;
#pragma unroll
        for (int c = 0; c < 8; c++) {
            p[c] = tf32r(fexp(acc[r][c]));   // round BEFORE summing
            sum += p[c];
        }
#pragma unroll
        for (int m = 1; m < 16; m <<= 1)
            sum += __shfl_xor_sync(0xffffffffu, sum, m);
        int row = n0 + ig * 4 + r;
        if (jg == 0)
            g_lpart[((size_t)z * 32 + kx) * NN + row] = sum;

        float* dst = P + (size_t)row * NN + m0 + jg * 8;
        *(float4*)(dst)     = make_float4(p[0], p[1], p[2], p[3]);
        *(float4*)(dst + 4) = make_float4(p[4], p[5], p[6], p[7]);
    }
}

// ---------------------------------------------------------------------------
// PV via mma.sync tf32. CTA: 128q x 256c (full C => P read ONCE).
// *** 512 threads / 16 warps (4/SMSP for latency hiding) ***
// warps: wq 0..3 (q-group of 32) x wc 0..3 (c-group of 64); acc 2x8x4.
// K in 32-chunks, double-buffered cp.async. Staged coalesced writeout.
// grid (32 qb, 8 z), dyn smem 110592 B.
// ---------------------------------------------------------------------------
#define PV_A0 0
#define PV_A1 (128*36)                 // 4608
#define PV_B0 (2*128*36)               // 9216
#define PV_B1 (PV_B0 + 256*36)         // 18432
#define PV_SMEM_FLOATS (PV_B1 + 256*36)   // 27648 floats = 110592 B
extern __shared__ float dyn_sm[];

__global__ __launch_bounds__(512)
void pv_mma_kernel()
{
    float* sm = dyn_sm;
    const int t    = threadIdx.x;
    const int lane = t & 31;
    const int warp = t >> 5;            // 0..15
    const int wq   = warp & 3;          // q-group of 32
    const int wc   = warp >> 2;         // c-group of 64 (0..3)
    const int qb   = blockIdx.x;
    const int z    = blockIdx.y;
    const int b    = z >> 1, a = z & 1;
    const int n0   = qb * 128;

    const float* P = g_p + (size_t)z * PPLANE + (size_t)n0 * NN;
    const float* V = g_v + ((size_t)a * BATCH + b) * (size_t)CC * NN;
    const uint32_t sm0 = smem_u32(sm);

    auto load_chunk = [&](int buf, int kc) {
        const int m0 = kc * 32;
        const uint32_t pd = sm0 + (uint32_t)(buf ? PV_A1 : PV_A0) * 4;
        const uint32_t vd = sm0 + (uint32_t)(buf ? PV_B1 : PV_B0) * 4;
#pragma unroll
        for (int i = 0; i < 2; i++) {           // P: 128 rows x 32 k = 1024 f4
            int f = t + 512 * i;
            int row = f >> 3, cg = f & 7;
            cpasync16(pd + (uint32_t)(row * 36 + cg * 4) * 4,
                      P + (size_t)row * NN + m0 + cg * 4);
        }
#pragma unroll
        for (int i = 0; i < 4; i++) {           // V: 256 rows x 32 k = 2048 f4
            int f = t + 512 * i;
            int row = f >> 3, cg = f & 7;
            cpasync16(vd + (uint32_t)(row * 36 + cg * 4) * 4,
                      V + (size_t)row * NN + m0 + cg * 4);
        }
        CP_COMMIT();
    };

    float acc[2][8][4];
#pragma unroll
    for (int mt = 0; mt < 2; mt++)
#pragma unroll
        for (int nt = 0; nt < 8; nt++)
#pragma unroll
            for (int e = 0; e < 4; e++) acc[mt][nt][e] = 0.f;

    const int r4 = lane >> 2;
    const int c4 = lane & 3;

    load_chunk(0, 0);
    for (int kc = 0; kc < 128; kc++) {
        const int buf = kc & 1;
        if (kc < 127) load_chunk(buf ^ 1, kc + 1);
        if (kc < 127) { CP_WAIT(1); } else { CP_WAIT(0); }
        __syncthreads();

        const float* Ps = sm + (buf ? PV_A1 : PV_A0);
        const float* Vs = sm + (buf ? PV_B1 : PV_B0);
#pragma unroll
        for (int ks = 0; ks < 4; ks++) {
            const int kcol = ks * 8 + c4;
            uint32_t A[2][4];
#pragma unroll
            for (int mt = 0; mt < 2; mt++) {
                const int rb = wq * 32 + mt * 16;
                A[mt][0] = __float_as_uint(Ps[(rb + r4)     * 36 + kcol]);
                A[mt][1] = __float_as_uint(Ps[(rb + r4 + 8) * 36 + kcol]);
                A[mt][2] = __float_as_uint(Ps[(rb + r4)     * 36 + kcol + 4]);
                A[mt][3] = __float_as_uint(Ps[(rb + r4 + 8) * 36 + kcol + 4]);
            }
#pragma unroll
            for (int nt = 0; nt < 8; nt++) {
                const int cb = wc * 64 + nt * 8;
                uint32_t B0 = __float_as_uint(Vs[(cb + r4) * 36 + kcol]);
                uint32_t B1 = __float_as_uint(Vs[(cb + r4) * 36 + kcol + 4]);
                mma_tf32(acc[0][nt], A[0], B0, B1);
                mma_tf32(acc[1][nt], A[1], B0, B1);
            }
        }
        __syncthreads();
    }

    // row-sum normalizers (deterministic) -> sm[0..127] (A region, now free)
    if (t < 128) {
        float s = 0.f;
#pragma unroll
        for (int x = 0; x < 32; x++)
            s += g_lpart[((size_t)z * 32 + x) * NN + n0 + t];
        sm[t] = 1.f / s;
    }
    __syncthreads();

    // staged coalesced writeout: two c-halves of 128 through B region
    float* stage = sm + PV_B0;          // 128 x pitch-132 floats (16896 <= 18432)
    const int crow = t >> 2;            // 0..127
    const int qseg = (t & 3) * 32;
    for (int h = 0; h < 2; h++) {
        if ((wc >> 1) == h) {
#pragma unroll
            for (int mt = 0; mt < 2; mt++)
#pragma unroll
                for (int nt = 0; nt < 8; nt++)
#pragma unroll
                    for (int e = 0; e < 4; e++) {
                        int ql = wq * 32 + mt * 16 + r4 + ((e >= 2) ? 8 : 0);
                        int cl = (wc & 1) * 64 + nt * 8 + 2 * c4 + (e & 1);
                        stage[cl * 132 + ql] = tf32r(acc[mt][nt][e] * sm[ql]);
                    }
        }
        __syncthreads();
        {
            float* dst = g_cat + ((size_t)b * CIN + a * 256 + h * 128 + crow) * NN + n0 + qseg;
            const float* src = stage + crow * 132 + qseg;
#pragma unroll
            for (int u = 0; u < 8; u++)
                *(float4*)(dst + u * 4) = *(const float4*)(src + u * 4);
        }
        __syncthreads();
    }
}

// ---------------------------------------------------------------------------
// Round Wc to tf32 (rna) into g_wt.
// ---------------------------------------------------------------------------
__global__ __launch_bounds__(256)
void round_w_kernel(const float* __restrict__ W)
{
    int i = blockIdx.x * 256 + threadIdx.x;
    float4 v = ((const float4*)W)[i];
    v.x = tf32r(v.x); v.y = tf32r(v.y); v.z = tf32r(v.z); v.w = tf32r(v.w);
    ((float4*)g_wt)[i] = v;
}

// ---------------------------------------------------------------------------
// Final 1x1 conv on tf32 mma + BN(eval) + LeakyReLU fused. [R10-proven]
// ---------------------------------------------------------------------------
#define OC_A0 0
#define OC_A1 (128*36)
#define OC_B0 (2*128*36)
#define OC_B1 (OC_B0 + 32*136)
#define OC_SMEM_FLOATS (OC_B1 + 32*136)   // 17920 floats = 71680 B

__global__ __launch_bounds__(256)
void outconv_mma_kernel(const float* __restrict__ bias, float* __restrict__ Y,
                        const float* __restrict__ gamma, const float* __restrict__ beta)
{
    float* sm = dyn_sm;
    const int t    = threadIdx.x;
    const int lane = t & 31;
    const int warp = t >> 5;
    const int wq   = warp & 3;
    const int wc   = warp >> 2;
    const int nb0  = blockIdx.x * 128;
    const int o0   = blockIdx.y * 128;
    const int b    = blockIdx.z;

    const float* Wt = g_wt + (size_t)o0 * CIN;
    const float* X  = g_cat + (size_t)b * CIN * NN;
    float* Yb = Y + (size_t)b * COUT * NN;
    const uint32_t sm0 = smem_u32(sm);

    auto load_chunk = [&](int buf, int kc) {
        const int k0 = kc * 32;
        const uint32_t ad = sm0 + (uint32_t)(buf ? OC_A1 : OC_A0) * 4;
        const uint32_t bd = sm0 + (uint32_t)(buf ? OC_B1 : OC_B0) * 4;
#pragma unroll
        for (int i = 0; i < 4; i++) {
            int f = t + 256 * i;
            int row = f >> 3, cg = f & 7;
            cpasync16(ad + (uint32_t)(row * 36 + cg * 4) * 4,
                      Wt + (size_t)row * CIN + k0 + cg * 4);
        }
#pragma unroll
        for (int i = 0; i < 4; i++) {
            int f = t + 256 * i;
            int row = f >> 5, cg = f & 31;
            cpasync16(bd + (uint32_t)(row * 136 + cg * 4) * 4,
                      X + (size_t)(k0 + row) * NN + nb0 + cg * 4);
        }
        CP_COMMIT();
    };

    float acc[2][8][4];
#pragma unroll
    for (int mt = 0; mt < 2; mt++)
#pragma unroll
        for (int nt = 0; nt < 8; nt++)
#pragma unroll
            for (int e = 0; e < 4; e++) acc[mt][nt][e] = 0.f;

    const int r4 = lane >> 2;
    const int c4 = lane & 3;

    load_chunk(0, 0);
    for (int kc = 0; kc < 16; kc++) {
        const int buf = kc & 1;
        if (kc < 15) load_chunk(buf ^ 1, kc + 1);
        if (kc < 15) { CP_WAIT(1); } else { CP_WAIT(0); }
        __syncthreads();

        const float* As = sm + (buf ? OC_A1 : OC_A0);
        const float* Bs = sm + (buf ? OC_B1 : OC_B0);
#pragma unroll
        for (int ks = 0; ks < 4; ks++) {
            const int kcol = ks * 8 + c4;
            uint32_t A[2][4];
#pragma unroll
            for (int mt = 0; mt < 2; mt++) {
                const int rb = wq * 32 + mt * 16;
                A[mt][0] = __float_as_uint(As[(rb + r4)     * 36 + kcol]);
                A[mt][1] = __float_as_uint(As[(rb + r4 + 8) * 36 + kcol]);
                A[mt][2] = __float_as_uint(As[(rb + r4)     * 36 + kcol + 4]);
                A[mt][3] = __float_as_uint(As[(rb + r4 + 8) * 36 + kcol + 4]);
            }
#pragma unroll
            for (int nt = 0; nt < 8; nt++) {
                const int nb = wc * 64 + nt * 8;
                uint32_t B0 = __float_as_uint(Bs[kcol * 136 + nb + r4]);
                uint32_t B1 = __float_as_uint(Bs[(kcol + 4) * 136 + nb + r4]);
                mma_tf32(acc[0][nt], A[0], B0, B1);
                mma_tf32(acc[1][nt], A[1], B0, B1);
            }
        }
        __syncthreads();
    }

    float* stage = sm;   // 128*132 floats
#pragma unroll
    for (int mt = 0; mt < 2; mt++)
#pragma unroll
        for (int nt = 0; nt < 8; nt++)
#pragma unroll
            for (int e = 0; e < 4; e++) {
                int ol = wq * 32 + mt * 16 + r4 + ((e >= 2) ? 8 : 0);
                int nl = wc * 64 + nt * 8 + 2 * c4 + (e & 1);
                stage[ol * 132 + nl] = acc[mt][nt][e];
            }
    __syncthreads();

    const float inv_bn = rsqrtf(1.0f + 1e-5f);
    {
        const int ol = t >> 1;
        const int o  = o0 + ol;
        const int nc = (t & 1) * 64;
        const float bv = bias[o];
        const float g  = gamma[o] * inv_bn;
        const float be = beta[o];
        float* dst = Yb + (size_t)o * NN + nb0 + nc;
        const float* src = stage + ol * 132 + nc;
#pragma unroll
        for (int u = 0; u < 16; u++) {
            float4 v = *(const float4*)(src + u * 4);
            float w[4] = {v.x, v.y, v.z, v.w};
#pragma unroll
            for (int q = 0; q < 4; q++) {
                float y = w[q] + bv;
                y = y * g + be;
                w[q] = (y > 0.f) ? y : 0.2f * y;
            }
            *(float4*)(dst + u * 4) = make_float4(w[0], w[1], w[2], w[3]);
        }
    }
}

// ---------------------------------------------------------------------------
// Launch
// ---------------------------------------------------------------------------
extern "C" void kernel_launch(void* const* d_in, const int* in_sizes, int n_in,
                              void* d_out, int out_size)
{
    const float* x   = (const float*)d_in[0];
    const float* Wq1 = (const float*)d_in[1];
    const float* bq1 = (const float*)d_in[2];
    const float* Wk1 = (const float*)d_in[3];
    const float* bk1 = (const float*)d_in[4];
    const float* Wv1 = (const float*)d_in[5];
    const float* bv1 = (const float*)d_in[6];
    const float* Wq2 = (const float*)d_in[7];
    const float* bq2 = (const float*)d_in[8];
    const float* Wk2 = (const float*)d_in[9];
    const float* bk2 = (const float*)d_in[10];
    const float* Wv2 = (const float*)d_in[11];
    const float* bv2 = (const float*)d_in[12];
    const float* Wc  = (const float*)d_in[13];
    const float* bc  = (const float*)d_in[14];
    const float* gam = (const float*)d_in[15];
    const float* bet = (const float*)d_in[16];
    float* out = (float*)d_out;

    proj_kernel<<<dim3(16, 20, BATCH), 256>>>(x,
        Wq1, bq1, Wk1, bk1, Wv1, bv1,
        Wq2, bq2, Wk2, bk2, Wv2, bv2);

    round_w_kernel<<<256, 256>>>(Wc);

    qk_exp_kernel<<<dim3(32, 64, 8), 256>>>();

    const int pv_smem = PV_SMEM_FLOATS * (int)sizeof(float);   // 110592 B
    cudaFuncSetAttribute(pv_mma_kernel,
                         cudaFuncAttributeMaxDynamicSharedMemorySize, pv_smem);
    pv_mma_kernel<<<dim3(32, 8), 512, pv_smem>>>();

    const int oc_smem = OC_SMEM_FLOATS * (int)sizeof(float);   // 71680 B
    cudaFuncSetAttribute(outconv_mma_kernel,
                         cudaFuncAttributeMaxDynamicSharedMemorySize, oc_smem);
    outconv_mma_kernel<<<dim3(32, 4, BATCH), 256, oc_smem>>>(bc, out, gam, bet);
}